// round 1
// baseline (speedup 1.0000x reference)
#include <cuda_runtime.h>
#include <math.h>

// Problem constants
#define NB    32
#define NH    12
#define GRID  14          // GH == GW
#define LTOK  196         // GRID*GRID
#define DHEAD 64
#define NSTEP 13          // steps 1..13
#define NBH   (NB * NH)   // 384 blocks

// out[b,h,m,d] = x[b,h,m,d]
//             + sum_{dir,step valid} C[h][dir][step][d] * x[b,h,neighbor(m,dir,step),d]
// where C[h][dir][step][d] = sd(step)*P[dir*4+si][d][h] + nd(step)*P[dir*4+si+1][d][h]
// and P = param_1 + param_2. Exactly 13 vertical + 13 horizontal taps per output.

__global__ __launch_bounds__(256, 3)
void save_kernel(const float* __restrict__ x,
                 const float* __restrict__ p1,
                 const float* __restrict__ p2,
                 float* __restrict__ out)
{
    extern __shared__ float sm[];
    float* xs = sm;                    // LTOK*DHEAD = 12544 floats (50176 B)
    float* Cs = sm + LTOK * DHEAD;     // 4*NSTEP*DHEAD = 3328 floats (13312 B)

    __shared__ float sd_s[NSTEP], nd_s[NSTEP];
    __shared__ int   si_s[NSTEP];

    const int bh  = blockIdx.x;           // b*NH + h
    const int hd  = bh % NH;              // head index
    const int tid = threadIdx.x;

    const float* xb = x   + (size_t)bh * (LTOK * DHEAD);
    float*       ob = out + (size_t)bh * (LTOK * DHEAD);

    // --- step weights (double precision, matches reference table build) ---
    if (tid < NSTEP) {
        int step = tid + 1;
        double interp = 3.0 * (double)(step - 1) / 13.0;
        int si = (int)interp;
        double dist = exp(-(double)(step * step) / 196.0);
        sd_s[tid] = (float)(dist * (1.0 - (interp - (double)si)));
        nd_s[tid] = (float)(dist * (interp - (double)si));
        si_s[tid] = si;
    }

    // --- load x tile into smem (vectorized) ---
    {
        const float4* x4  = (const float4*)xb;
        float4*       xs4 = (float4*)xs;
        #pragma unroll 4
        for (int i = tid; i < (LTOK * DHEAD) / 4; i += 256)
            xs4[i] = x4[i];
    }
    __syncthreads();

    // --- build per-head coefficients C[dir][step][d] ---
    // P layout: param[(k*DHEAD + d)*NH + h]
    for (int i = tid; i < 4 * NSTEP * DHEAD; i += 256) {
        int d    = i & (DHEAD - 1);
        int sidx = (i >> 6) % NSTEP;
        int dir  = i / (NSTEP * DHEAD);
        int si   = si_s[sidx];
        int k0   = dir * 4 + si;
        int ia   = (k0 * DHEAD + d) * NH + hd;
        int ib   = ((k0 + 1) * DHEAD + d) * NH + hd;
        float pa = p1[ia] + p2[ia];
        float pb = p1[ib] + p2[ib];
        Cs[i] = sd_s[sidx] * pa + nd_s[sidx] * pb;
    }
    __syncthreads();

    // ================= V phase: out = x + vertical conv =================
    // tasks: (w, d) pairs -> 14*64 = 896; column of 14 x-values in registers
    for (int v = tid; v < GRID * DHEAD; v += 256) {
        int d = v & (DHEAD - 1);
        int w = v >> 6;

        float xc[GRID];
        #pragma unroll
        for (int hh = 0; hh < GRID; hh++)
            xc[hh] = xs[(hh * GRID + w) * DHEAD + d];

        float c0[NSTEP], c1[NSTEP];
        #pragma unroll
        for (int s = 0; s < NSTEP; s++) {
            c0[s] = Cs[(0 * NSTEP + s) * DHEAD + d];   // top (h - s)
            c1[s] = Cs[(1 * NSTEP + s) * DHEAD + d];   // bottom (h + s)
        }

        #pragma unroll
        for (int hh = 0; hh < GRID; hh++) {
            float acc = xc[hh];
            #pragma unroll
            for (int s = 1; s <= hh; s++)
                acc = fmaf(c0[s - 1], xc[hh - s], acc);
            #pragma unroll
            for (int s = 1; s <= NSTEP - hh; s++)
                acc = fmaf(c1[s - 1], xc[hh + s], acc);
            ob[(hh * GRID + w) * DHEAD + d] = acc;
        }
    }
    __syncthreads();   // orders V-phase global stores before H-phase RMW (same block)

    // ================= H phase: out += horizontal conv =================
    // tasks: (hrow, d) pairs -> 14*64 = 896; row of 14 x-values in registers
    for (int v = tid; v < GRID * DHEAD; v += 256) {
        int d  = v & (DHEAD - 1);
        int hr = v >> 6;

        float xr[GRID];
        #pragma unroll
        for (int ww = 0; ww < GRID; ww++)
            xr[ww] = xs[(hr * GRID + ww) * DHEAD + d];

        float c2[NSTEP], c3[NSTEP];
        #pragma unroll
        for (int s = 0; s < NSTEP; s++) {
            c2[s] = Cs[(2 * NSTEP + s) * DHEAD + d];   // left (w - s)
            c3[s] = Cs[(3 * NSTEP + s) * DHEAD + d];   // right (w + s)
        }

        #pragma unroll
        for (int ww = 0; ww < GRID; ww++) {
            float acc = 0.0f;
            #pragma unroll
            for (int s = 1; s <= ww; s++)
                acc = fmaf(c2[s - 1], xr[ww - s], acc);
            #pragma unroll
            for (int s = 1; s <= NSTEP - ww; s++)
                acc = fmaf(c3[s - 1], xr[ww + s], acc);
            int idx = (hr * GRID + ww) * DHEAD + d;
            ob[idx] += acc;   // exclusive per element; V result visible via syncthreads
        }
    }
}

extern "C" void kernel_launch(void* const* d_in, const int* in_sizes, int n_in,
                              void* d_out, int out_size)
{
    // metadata order: x, table, param_1, param_2  (table is recomputed analytically)
    const float* x  = (const float*)d_in[0];
    const float* p1 = (const float*)d_in[2];
    const float* p2 = (const float*)d_in[3];
    float*       out = (float*)d_out;

    const int smem_bytes = (LTOK * DHEAD + 4 * NSTEP * DHEAD) * (int)sizeof(float); // 63488
    cudaFuncSetAttribute(save_kernel, cudaFuncAttributeMaxDynamicSharedMemorySize, smem_bytes);
    save_kernel<<<NBH, 256, smem_bytes>>>(x, p1, p2, out);
}